// round 10
// baseline (speedup 1.0000x reference)
#include <cuda_runtime.h>
#include <cuda_fp16.h>
#include <cstdint>

#define BB 8
#define SS 1024
#define NH 16
#define DKV 64
#define DMODEL 1024
#define MTOT (BB*SS)

// fp16 hi/lo splits of X inputs; weights rounded to fp16, transposed [n][k]
__device__ __half g_xhi[3][MTOT*DMODEL];
__device__ __half g_xlo[3][MTOT*DMODEL];
__device__ __half g_wt[3][DMODEL*DMODEL];

// projected tensors, [bh][s][d]; q pre-scaled by 1/8 and split hi/lo
__device__ __half g_qh[BB*NH*SS*DKV];
__device__ __half g_ql[BB*NH*SS*DKV];
__device__ __half g_kf[BB*NH*SS*DKV];
__device__ __half g_vf[BB*NH*SS*DKV];

static __device__ __forceinline__ uint32_t s2u(const void* p) {
    uint32_t a;
    asm("{ .reg .u64 t; cvta.to.shared.u64 t, %1; cvt.u32.u64 %0, t; }"
        : "=r"(a) : "l"(p));
    return a;
}

static __device__ __forceinline__ void cp16(uint32_t s, const void* g) {
    asm volatile("cp.async.cg.shared.global [%0], [%1], 16;" :: "r"(s), "l"(g));
}
#define CP_COMMIT() asm volatile("cp.async.commit_group;" ::: "memory")
#define CP_WAIT1()  asm volatile("cp.async.wait_group 1;" ::: "memory")

#define LDSM4(r, addr) \
    asm volatile("ldmatrix.sync.aligned.m8n8.x4.shared.b16 {%0,%1,%2,%3}, [%4];" \
        : "=r"((r)[0]), "=r"((r)[1]), "=r"((r)[2]), "=r"((r)[3]) : "r"(addr))

#define LDSM4T(r, addr) \
    asm volatile("ldmatrix.sync.aligned.m8n8.x4.trans.shared.b16 {%0,%1,%2,%3}, [%4];" \
        : "=r"((r)[0]), "=r"((r)[1]), "=r"((r)[2]), "=r"((r)[3]) : "r"(addr))

#define MMA16816(d, a, b) \
    asm volatile("mma.sync.aligned.m16n8k16.row.col.f32.f16.f16.f32 " \
        "{%0,%1,%2,%3}, {%4,%5,%6,%7}, {%8,%9}, {%0,%1,%2,%3};" \
        : "+f"((d)[0]), "+f"((d)[1]), "+f"((d)[2]), "+f"((d)[3]) \
        : "r"((a)[0]), "r"((a)[1]), "r"((a)[2]), "r"((a)[3]), \
          "r"((b)[0]), "r"((b)[1]))

static __device__ __forceinline__ uint32_t pack2h(__half x, __half y) {
    return (uint32_t)__half_as_ushort(x) | ((uint32_t)__half_as_ushort(y) << 16);
}

// vectorized hi/lo split of a float pair
static __device__ __forceinline__ void split_pack2(float x, float y,
                                                   uint32_t& hp, uint32_t& lp) {
    __half2 h = __float22half2_rn(make_float2(x, y));
    float2 hb = __half22float2(h);
    __half2 l = __float22half2_rn(make_float2(x - hb.x, y - hb.y));
    hp = *(uint32_t*)&h;
    lp = *(uint32_t*)&l;
}

static __device__ __forceinline__ uint32_t round2h(float x, float y) {
    __half2 h = __float22half2_rn(make_float2(x, y));
    return *(uint32_t*)&h;
}

// ---------------------------------------------------------------------------
// Prep 1: X -> (hi, lo) fp16, row-major [8192, 1024]
// ---------------------------------------------------------------------------
__global__ __launch_bounds__(256)
void convert_x_kernel(const float* __restrict__ Q, const float* __restrict__ K,
                      const float* __restrict__ V)
{
    const int z = blockIdx.y;
    const float* X = (z == 0) ? Q : (z == 1) ? K : V;
    size_t i = ((size_t)blockIdx.x * 256 + threadIdx.x) * 4;
    float4 v = *(const float4*)(X + i);
    uint2 h, l;
    split_pack2(v.x, v.y, h.x, l.x);
    split_pack2(v.z, v.w, h.y, l.y);
    *(uint2*)&g_xhi[z][i] = h;
    *(uint2*)&g_xlo[z][i] = l;
}

// ---------------------------------------------------------------------------
// Prep 2: W [k][n] -> Wt fp16 (rounded) [n][k]
// ---------------------------------------------------------------------------
__global__ __launch_bounds__(256)
void conv_w_kernel(const float* __restrict__ Wq, const float* __restrict__ Wk,
                   const float* __restrict__ Wv)
{
    const int z = blockIdx.z;
    const float* W = (z == 0) ? Wq : (z == 1) ? Wk : Wv;
    __shared__ float tile[32][33];
    const int tx = threadIdx.x;
    const int ty = threadIdx.y;
    const int n0 = blockIdx.x * 32;
    const int k0 = blockIdx.y * 32;
    #pragma unroll
    for (int i = 0; i < 4; i++)
        tile[ty + i * 8][tx] = W[(size_t)(k0 + ty + i * 8) * DMODEL + n0 + tx];
    __syncthreads();
    #pragma unroll
    for (int i = 0; i < 4; i++) {
        int n = ty + i * 8;
        g_wt[z][(size_t)(n0 + n) * DMODEL + k0 + tx] = __float2half_rn(tile[tx][n]);
    }
}

// ---------------------------------------------------------------------------
// mma.sync fp16x2 projection GEMM, 2-stage cp.async, 2 CTAs/SM.
// ---------------------------------------------------------------------------
#define PSTAGE 49152   // Xh 16K | Xl 16K | W 16K
#define PROJ_SMEM (1024 + 2 * PSTAGE)   // 99328

__global__ __launch_bounds__(256, 2)
void proj_mma_kernel(const float* __restrict__ bq, const float* __restrict__ bk,
                     const float* __restrict__ bv)
{
    extern __shared__ char sm[];
    const uint32_t sb = s2u(sm);
    const int t    = threadIdx.x;
    const int wid  = t >> 5;
    const int lane = t & 31;
    const int bm   = blockIdx.x * 128;
    const int bn   = blockIdx.y * 128;
    const int z    = blockIdx.z;

    const float* bias = (z == 0) ? bq : (z == 1) ? bk : bv;
    const float scale = (z == 0) ? 0.125f : 1.0f;
    const __half* Xh = g_xhi[z];
    const __half* Xl = g_xlo[z];
    const __half* Wt = g_wt[z];

    float* biasS = (float*)sm;
    if (t < 128) biasS[t] = bias[bn + t];

    const int wm = wid >> 2;
    const int wn = wid & 3;

    float acc[4][4][4];
    #pragma unroll
    for (int i = 0; i < 4; i++)
        #pragma unroll
        for (int j = 0; j < 4; j++)
            #pragma unroll
            for (int r = 0; r < 4; r++) acc[i][j][r] = 0.0f;

    #define LOAD_STAGE(c, buf) do {                                            \
        const uint32_t base_ = sb + 1024 + (buf) * PSTAGE;                     \
        const int k0_ = (c) * 64;                                              \
        _Pragma("unroll")                                                      \
        for (int r_ = 0; r_ < 4; r_++) {                                       \
            int idx_ = t + r_ * 256;                                           \
            int row_ = idx_ >> 3;                                              \
            int ch_  = idx_ & 7;                                               \
            uint32_t so_ = (uint32_t)(row_ * 128) + ((ch_ ^ (row_ & 7)) * 16); \
            size_t ga_ = (size_t)(bm + row_) * DMODEL + k0_ + ch_ * 8;         \
            size_t gb_ = (size_t)(bn + row_) * DMODEL + k0_ + ch_ * 8;         \
            cp16(base_ + so_,          Xh + ga_);                              \
            cp16(base_ + 16384 + so_,  Xl + ga_);                              \
            cp16(base_ + 32768 + so_,  Wt + gb_);                              \
        }                                                                      \
        CP_COMMIT();                                                           \
    } while (0)

    LOAD_STAGE(0, 0);
    LOAD_STAGE(1, 1);

    for (int c = 0; c < 16; c++) {
        CP_WAIT1();
        __syncthreads();
        const uint32_t base = sb + 1024 + (c & 1) * PSTAGE;
        #pragma unroll
        for (int ks = 0; ks < 4; ks++) {
            uint32_t aH[4][4], aL[4][4], bF[4][2];
            const int chunk = 2 * ks + (lane >> 4);
            #pragma unroll
            for (int mi = 0; mi < 4; mi++) {
                int r = wm * 64 + mi * 16 + (lane & 15);
                uint32_t so = base + (uint32_t)(r * 128) + ((chunk ^ (r & 7)) * 16);
                LDSM4(aH[mi], so);
                LDSM4(aL[mi], so + 16384);
            }
            #pragma unroll
            for (int p = 0; p < 2; p++) {
                int r = wn * 32 + p * 16 + (lane & 15);
                uint32_t so = base + 32768 + (uint32_t)(r * 128) + ((chunk ^ (r & 7)) * 16);
                uint32_t q[4];
                LDSM4(q, so);
                bF[p * 2][0] = q[0]; bF[p * 2][1] = q[2];
                bF[p * 2 + 1][0] = q[1]; bF[p * 2 + 1][1] = q[3];
            }
            #pragma unroll
            for (int mi = 0; mi < 4; mi++)
                #pragma unroll
                for (int nf = 0; nf < 4; nf++) {
                    MMA16816(acc[mi][nf], aH[mi], bF[nf]);
                    MMA16816(acc[mi][nf], aL[mi], bF[nf]);
                }
        }
        __syncthreads();
        if (c < 14) { LOAD_STAGE(c + 2, c & 1); }
        else        { CP_COMMIT(); }
    }

    // epilogue -> [bh][s][d]: q split hi/lo; k,v single fp16
    #pragma unroll
    for (int mi = 0; mi < 4; mi++) {
        #pragma unroll
        for (int nf = 0; nf < 4; nf++) {
            int nloc = wn * 32 + nf * 8 + (lane & 3) * 2;
            int n = bn + nloc;
            int h = n >> 6;
            int d = n & 63;
            float b0 = biasS[nloc], b1 = biasS[nloc + 1];
            #pragma unroll
            for (int half_ = 0; half_ < 2; half_++) {
                int m = bm + wm * 64 + mi * 16 + (lane >> 2) + half_ * 8;
                int bb = m >> 10;
                int s  = m & 1023;
                float y0 = (acc[mi][nf][half_ * 2 + 0] + b0) * scale;
                float y1 = (acc[mi][nf][half_ * 2 + 1] + b1) * scale;
                size_t o = (((size_t)(bb * NH + h) * SS + s) * DKV + d) >> 1;
                if (z == 0) {
                    uint32_t hp, lp;
                    split_pack2(y0, y1, hp, lp);
                    ((uint32_t*)g_qh)[o] = hp;
                    ((uint32_t*)g_ql)[o] = lp;
                } else {
                    uint32_t hp = pack2h(__float2half_rn(y0), __float2half_rn(y1));
                    if (z == 1) ((uint32_t*)g_kf)[o] = hp;
                    else        ((uint32_t*)g_vf)[o] = hp;
                }
            }
        }
    }
}

// ---------------------------------------------------------------------------
// Attention via mma.sync fp16, 32-query-row warp tiles, 1 CTA/SM.
// CTA = 256 queries (8 warps x 2 m16 blocks), loop over 128-key tiles.
// K/V fragments shared across the 2 query blocks -> half the ldsm/addr work.
// ---------------------------------------------------------------------------
#define AST 32768          // stage: K 16K | V 16K
#define OS0 65536          // Qh 32K | Ql 32K
#define ATTN_SMEM (OS0 + 2 * AST)   // 131072

__global__ __launch_bounds__(256, 1)
void attn_mma_kernel(float* __restrict__ out)
{
    extern __shared__ char sm[];
    const uint32_t sb = s2u(sm);
    const int t    = threadIdx.x;
    const int w    = t >> 5;
    const int lane = t & 31;
    const int bh   = blockIdx.y;
    const int q0   = blockIdx.x * 256;

    const __half* Qh = g_qh + (size_t)bh * SS * DKV;
    const __half* Ql = g_ql + (size_t)bh * SS * DKV;
    const __half* Kf = g_kf + (size_t)bh * SS * DKV;
    const __half* Vf = g_vf + (size_t)bh * SS * DKV;

    // Q tiles (once): 256 rows x 128B, hi + lo
    #pragma unroll
    for (int r_ = 0; r_ < 8; r_++) {
        int idx = t + r_ * 256;
        int row = idx >> 3;
        int ch  = idx & 7;
        uint32_t so = (uint32_t)(row * 128) + ((ch ^ (row & 7)) * 16);
        cp16(sb + so,          Qh + (size_t)(q0 + row) * DKV + ch * 8);
        cp16(sb + 32768 + so,  Ql + (size_t)(q0 + row) * DKV + ch * 8);
    }
    CP_COMMIT();

    #define A_LOAD_STAGE(c, stg) do {                                          \
        const uint32_t base_ = sb + OS0 + (stg) * AST;                         \
        const int kt_ = (c) * 128;                                             \
        _Pragma("unroll")                                                      \
        for (int r_ = 0; r_ < 4; r_++) {                                       \
            int idx_ = t + r_ * 256;                                           \
            int row_ = idx_ >> 3;                                              \
            int ch_  = idx_ & 7;                                               \
            uint32_t so_ = (uint32_t)(row_ * 128) + ((ch_ ^ (row_ & 7)) * 16); \
            size_t g_ = (size_t)(kt_ + row_) * DKV + ch_ * 8;                  \
            cp16(base_ + so_,          Kf + g_);                               \
            cp16(base_ + 16384 + so_,  Vf + g_);                               \
        }                                                                      \
        CP_COMMIT();                                                           \
    } while (0)

    A_LOAD_STAGE(0, 0);
    A_LOAD_STAGE(1, 1);

    float ctx[2][8][4];
    #pragma unroll
    for (int b2 = 0; b2 < 2; b2++)
        #pragma unroll
        for (int f = 0; f < 8; f++)
            #pragma unroll
            for (int r = 0; r < 4; r++) ctx[b2][f][r] = 0.0f;
    float rs[2][2] = {{0.0f, 0.0f}, {0.0f, 0.0f}};

    for (int c = 0; c < 8; c++) {
        CP_WAIT1();
        __syncthreads();
        const uint32_t kbase = sb + OS0 + (c & 1) * AST;
        const uint32_t vbase = kbase + 16384;

        #pragma unroll
        for (int half_ = 0; half_ < 2; half_++) {
            // ---- QK for 64-key half, both query blocks ----
            float S[2][8][4];
            #pragma unroll
            for (int b2 = 0; b2 < 2; b2++)
                #pragma unroll
                for (int f = 0; f < 8; f++)
                    #pragma unroll
                    for (int r = 0; r < 4; r++) S[b2][f][r] = 0.0f;

            #pragma unroll
            for (int ks = 0; ks < 4; ks++) {
                const int chunk = 2 * ks + (lane >> 4);
                uint32_t aH[2][4], aL[2][4];
                #pragma unroll
                for (int b2 = 0; b2 < 2; b2++) {
                    int r = w * 32 + b2 * 16 + (lane & 15);
                    uint32_t so = sb + (uint32_t)(r * 128) + ((chunk ^ (r & 7)) * 16);
                    LDSM4(aH[b2], so);
                    LDSM4(aL[b2], so + 32768);
                }
                #pragma unroll
                for (int j = 0; j < 4; j++) {
                    int r = half_ * 64 + j * 16 + (lane & 15);
                    uint32_t so = kbase + (uint32_t)(r * 128) + ((chunk ^ (r & 7)) * 16);
                    uint32_t qk[4];
                    LDSM4(qk, so);
                    uint32_t b0[2] = {qk[0], qk[2]}, b1[2] = {qk[1], qk[3]};
                    #pragma unroll
                    for (int b2 = 0; b2 < 2; b2++) {
                        MMA16816(S[b2][2 * j],     aH[b2], b0);
                        MMA16816(S[b2][2 * j],     aL[b2], b0);
                        MMA16816(S[b2][2 * j + 1], aH[b2], b1);
                        MMA16816(S[b2][2 * j + 1], aL[b2], b1);
                    }
                }
            }

            // ---- exp + rowsum + P round-to-fp16 + PV (V frags shared) ----
            #pragma unroll
            for (int j = 0; j < 4; j++) {
                uint32_t aP[2][4];
                #pragma unroll
                for (int b2 = 0; b2 < 2; b2++) {
                    float e0 = __expf(S[b2][2 * j][0]),     e1 = __expf(S[b2][2 * j][1]);
                    float e2 = __expf(S[b2][2 * j][2]),     e3 = __expf(S[b2][2 * j][3]);
                    float e4 = __expf(S[b2][2 * j + 1][0]), e5 = __expf(S[b2][2 * j + 1][1]);
                    float e6 = __expf(S[b2][2 * j + 1][2]), e7 = __expf(S[b2][2 * j + 1][3]);
                    rs[b2][0] += (e0 + e1) + (e4 + e5);
                    rs[b2][1] += (e2 + e3) + (e6 + e7);
                    aP[b2][0] = round2h(e0, e1);
                    aP[b2][1] = round2h(e2, e3);
                    aP[b2][2] = round2h(e4, e5);
                    aP[b2][3] = round2h(e6, e7);
                }
                #pragma unroll
                for (int p = 0; p < 4; p++) {
                    int r  = half_ * 64 + j * 16 + (lane & 15);
                    int ch = p * 2 + (lane >> 4);
                    uint32_t so = vbase + (uint32_t)(r * 128) + ((ch ^ (r & 7)) * 16);
                    uint32_t vv[4];
                    LDSM4T(vv, so);
                    uint32_t b0[2] = {vv[0], vv[1]}, b1[2] = {vv[2], vv[3]};
                    #pragma unroll
                    for (int b2 = 0; b2 < 2; b2++) {
                        MMA16816(ctx[b2][2 * p],     aP[b2], b0);
                        MMA16816(ctx[b2][2 * p + 1], aP[b2], b1);
                    }
                }
            }
        }

        __syncthreads();
        if (c < 6) { A_LOAD_STAGE(c + 2, c & 1); }
        else       { CP_COMMIT(); }
    }

    const int bb = bh >> 4;
    const int h  = bh & 15;
    #pragma unroll
    for (int b2 = 0; b2 < 2; b2++) {
        float r0 = rs[b2][0], r1 = rs[b2][1];
        r0 += __shfl_xor_sync(0xFFFFFFFF, r0, 1);
        r0 += __shfl_xor_sync(0xFFFFFFFF, r0, 2);
        r1 += __shfl_xor_sync(0xFFFFFFFF, r1, 1);
        r1 += __shfl_xor_sync(0xFFFFFFFF, r1, 2);
        const float inv0 = 1.0f / (r0 + 1e-8f);
        const float inv1 = 1.0f / (r1 + 1e-8f);
        const int sLo = q0 + w * 32 + b2 * 16 + (lane >> 2);
        #pragma unroll
        for (int f = 0; f < 8; f++) {
            int d0 = f * 8 + (lane & 3) * 2;
            float2 v0, v1;
            v0.x = ctx[b2][f][0] * inv0; v0.y = ctx[b2][f][1] * inv0;
            v1.x = ctx[b2][f][2] * inv1; v1.y = ctx[b2][f][3] * inv1;
            *(float2*)&out[((size_t)(bb * SS + sLo) * DMODEL) + h * DKV + d0]     = v0;
            *(float2*)&out[((size_t)(bb * SS + sLo + 8) * DMODEL) + h * DKV + d0] = v1;
        }
    }
}

// ---------------------------------------------------------------------------
extern "C" void kernel_launch(void* const* d_in, const int* in_sizes, int n_in,
                              void* d_out, int out_size)
{
    const float* Q  = (const float*)d_in[0];
    const float* K  = (const float*)d_in[1];
    const float* V  = (const float*)d_in[2];
    const float* Wq = (const float*)d_in[3];
    const float* bq = (const float*)d_in[4];
    const float* Wk = (const float*)d_in[5];
    const float* bk = (const float*)d_in[6];
    const float* Wv = (const float*)d_in[7];
    const float* bv = (const float*)d_in[8];
    float* out = (float*)d_out;

    cudaFuncSetAttribute(proj_mma_kernel,
                         cudaFuncAttributeMaxDynamicSharedMemorySize, PROJ_SMEM);
    cudaFuncSetAttribute(attn_mma_kernel,
                         cudaFuncAttributeMaxDynamicSharedMemorySize, ATTN_SMEM);

    convert_x_kernel<<<dim3(MTOT * DMODEL / 1024, 3), 256>>>(Q, K, V);
    conv_w_kernel<<<dim3(32, 32, 3), dim3(32, 8)>>>(Wq, Wk, Wv);

    dim3 pg(MTOT / 128, DMODEL / 128, 3);
    proj_mma_kernel<<<pg, 256, PROJ_SMEM>>>(bq, bk, bv);

    dim3 ag(SS / 256, BB * NH);
    attn_mma_kernel<<<ag, 256, ATTN_SMEM>>>(out);
}

// round 11
// speedup vs baseline: 1.4820x; 1.4820x over previous
#include <cuda_runtime.h>
#include <cuda_fp16.h>
#include <cstdint>

#define BB 8
#define SS 1024
#define NH 16
#define DKV 64
#define DMODEL 1024
#define MTOT (BB*SS)

// X rounded to fp16; weights rounded to fp16, transposed [n][k]
__device__ __half g_x[3][MTOT*DMODEL];
__device__ __half g_wt[3][DMODEL*DMODEL];

// projected tensors, [bh][s][d]; q pre-scaled by 1/8 and split hi/lo
__device__ __half g_qh[BB*NH*SS*DKV];
__device__ __half g_ql[BB*NH*SS*DKV];
__device__ __half g_kf[BB*NH*SS*DKV];
__device__ __half g_vf[BB*NH*SS*DKV];

static __device__ __forceinline__ uint32_t s2u(const void* p) {
    uint32_t a;
    asm("{ .reg .u64 t; cvta.to.shared.u64 t, %1; cvt.u32.u64 %0, t; }"
        : "=r"(a) : "l"(p));
    return a;
}

static __device__ __forceinline__ void cp16(uint32_t s, const void* g) {
    asm volatile("cp.async.cg.shared.global [%0], [%1], 16;" :: "r"(s), "l"(g));
}
#define CP_COMMIT() asm volatile("cp.async.commit_group;" ::: "memory")
#define CP_WAIT1()  asm volatile("cp.async.wait_group 1;" ::: "memory")

#define LDSM4(r, addr) \
    asm volatile("ldmatrix.sync.aligned.m8n8.x4.shared.b16 {%0,%1,%2,%3}, [%4];" \
        : "=r"((r)[0]), "=r"((r)[1]), "=r"((r)[2]), "=r"((r)[3]) : "r"(addr))

#define LDSM4T(r, addr) \
    asm volatile("ldmatrix.sync.aligned.m8n8.x4.trans.shared.b16 {%0,%1,%2,%3}, [%4];" \
        : "=r"((r)[0]), "=r"((r)[1]), "=r"((r)[2]), "=r"((r)[3]) : "r"(addr))

#define MMA16816(d, a, b) \
    asm volatile("mma.sync.aligned.m16n8k16.row.col.f32.f16.f16.f32 " \
        "{%0,%1,%2,%3}, {%4,%5,%6,%7}, {%8,%9}, {%0,%1,%2,%3};" \
        : "+f"((d)[0]), "+f"((d)[1]), "+f"((d)[2]), "+f"((d)[3]) \
        : "r"((a)[0]), "r"((a)[1]), "r"((a)[2]), "r"((a)[3]), \
          "r"((b)[0]), "r"((b)[1]))

static __device__ __forceinline__ uint32_t pack2h(__half x, __half y) {
    return (uint32_t)__half_as_ushort(x) | ((uint32_t)__half_as_ushort(y) << 16);
}

static __device__ __forceinline__ void split_pack2(float x, float y,
                                                   uint32_t& hp, uint32_t& lp) {
    __half2 h = __float22half2_rn(make_float2(x, y));
    float2 hb = __half22float2(h);
    __half2 l = __float22half2_rn(make_float2(x - hb.x, y - hb.y));
    hp = *(uint32_t*)&h;
    lp = *(uint32_t*)&l;
}

static __device__ __forceinline__ uint32_t round2h(float x, float y) {
    __half2 h = __float22half2_rn(make_float2(x, y));
    return *(uint32_t*)&h;
}

// ---------------------------------------------------------------------------
// Prep 1: X -> fp16 (rounded), row-major [8192, 1024]
// ---------------------------------------------------------------------------
__global__ __launch_bounds__(256)
void convert_x_kernel(const float* __restrict__ Q, const float* __restrict__ K,
                      const float* __restrict__ V)
{
    const int z = blockIdx.y;
    const float* X = (z == 0) ? Q : (z == 1) ? K : V;
    size_t i = ((size_t)blockIdx.x * 256 + threadIdx.x) * 4;
    float4 v = *(const float4*)(X + i);
    uint2 h;
    h.x = round2h(v.x, v.y);
    h.y = round2h(v.z, v.w);
    *(uint2*)&g_x[z][i] = h;
}

// ---------------------------------------------------------------------------
// Prep 2: W [k][n] -> Wt fp16 (rounded) [n][k]
// ---------------------------------------------------------------------------
__global__ __launch_bounds__(256)
void conv_w_kernel(const float* __restrict__ Wq, const float* __restrict__ Wk,
                   const float* __restrict__ Wv)
{
    const int z = blockIdx.z;
    const float* W = (z == 0) ? Wq : (z == 1) ? Wk : Wv;
    __shared__ float tile[32][33];
    const int tx = threadIdx.x;
    const int ty = threadIdx.y;
    const int n0 = blockIdx.x * 32;
    const int k0 = blockIdx.y * 32;
    #pragma unroll
    for (int i = 0; i < 4; i++)
        tile[ty + i * 8][tx] = W[(size_t)(k0 + ty + i * 8) * DMODEL + n0 + tx];
    __syncthreads();
    #pragma unroll
    for (int i = 0; i < 4; i++) {
        int n = ty + i * 8;
        g_wt[z][(size_t)(n0 + n) * DMODEL + k0 + tx] = __float2half_rn(tile[tx][n]);
    }
}

// ---------------------------------------------------------------------------
// mma.sync fp16 projection GEMM (single product), 2-stage cp.async, 2 CTAs/SM.
// ---------------------------------------------------------------------------
#define PSTAGE 32768   // X 16K | W 16K
#define PROJ_SMEM (1024 + 2 * PSTAGE)   // 66560

__global__ __launch_bounds__(256, 2)
void proj_mma_kernel(const float* __restrict__ bq, const float* __restrict__ bk,
                     const float* __restrict__ bv)
{
    extern __shared__ char sm[];
    const uint32_t sb = s2u(sm);
    const int t    = threadIdx.x;
    const int wid  = t >> 5;
    const int lane = t & 31;
    const int bm   = blockIdx.x * 128;
    const int bn   = blockIdx.y * 128;
    const int z    = blockIdx.z;

    const float* bias = (z == 0) ? bq : (z == 1) ? bk : bv;
    const float scale = (z == 0) ? 0.125f : 1.0f;
    const __half* Xf = g_x[z];
    const __half* Wt = g_wt[z];

    float* biasS = (float*)sm;
    if (t < 128) biasS[t] = bias[bn + t];

    const int wm = wid >> 2;
    const int wn = wid & 3;

    float acc[4][4][4];
    #pragma unroll
    for (int i = 0; i < 4; i++)
        #pragma unroll
        for (int j = 0; j < 4; j++)
            #pragma unroll
            for (int r = 0; r < 4; r++) acc[i][j][r] = 0.0f;

    #define LOAD_STAGE(c, buf) do {                                            \
        const uint32_t base_ = sb + 1024 + (buf) * PSTAGE;                     \
        const int k0_ = (c) * 64;                                              \
        _Pragma("unroll")                                                      \
        for (int r_ = 0; r_ < 4; r_++) {                                       \
            int idx_ = t + r_ * 256;                                           \
            int row_ = idx_ >> 3;                                              \
            int ch_  = idx_ & 7;                                               \
            uint32_t so_ = (uint32_t)(row_ * 128) + ((ch_ ^ (row_ & 7)) * 16); \
            size_t ga_ = (size_t)(bm + row_) * DMODEL + k0_ + ch_ * 8;         \
            size_t gb_ = (size_t)(bn + row_) * DMODEL + k0_ + ch_ * 8;         \
            cp16(base_ + so_,          Xf + ga_);                              \
            cp16(base_ + 16384 + so_,  Wt + gb_);                              \
        }                                                                      \
        CP_COMMIT();                                                           \
    } while (0)

    LOAD_STAGE(0, 0);
    LOAD_STAGE(1, 1);

    for (int c = 0; c < 16; c++) {
        CP_WAIT1();
        __syncthreads();
        const uint32_t base = sb + 1024 + (c & 1) * PSTAGE;
        #pragma unroll
        for (int ks = 0; ks < 4; ks++) {
            uint32_t aF[4][4], bF[4][2];
            const int chunk = 2 * ks + (lane >> 4);
            #pragma unroll
            for (int mi = 0; mi < 4; mi++) {
                int r = wm * 64 + mi * 16 + (lane & 15);
                uint32_t so = base + (uint32_t)(r * 128) + ((chunk ^ (r & 7)) * 16);
                LDSM4(aF[mi], so);
            }
            #pragma unroll
            for (int p = 0; p < 2; p++) {
                int r = wn * 32 + p * 16 + (lane & 15);
                uint32_t so = base + 16384 + (uint32_t)(r * 128) + ((chunk ^ (r & 7)) * 16);
                uint32_t q[4];
                LDSM4(q, so);
                bF[p * 2][0] = q[0]; bF[p * 2][1] = q[2];
                bF[p * 2 + 1][0] = q[1]; bF[p * 2 + 1][1] = q[3];
            }
            #pragma unroll
            for (int mi = 0; mi < 4; mi++)
                #pragma unroll
                for (int nf = 0; nf < 4; nf++)
                    MMA16816(acc[mi][nf], aF[mi], bF[nf]);
        }
        __syncthreads();
        if (c < 14) { LOAD_STAGE(c + 2, c & 1); }
        else        { CP_COMMIT(); }
    }

    // epilogue -> [bh][s][d]: q split hi/lo; k,v single fp16
    #pragma unroll
    for (int mi = 0; mi < 4; mi++) {
        #pragma unroll
        for (int nf = 0; nf < 4; nf++) {
            int nloc = wn * 32 + nf * 8 + (lane & 3) * 2;
            int n = bn + nloc;
            int h = n >> 6;
            int d = n & 63;
            float b0 = biasS[nloc], b1 = biasS[nloc + 1];
            #pragma unroll
            for (int half_ = 0; half_ < 2; half_++) {
                int m = bm + wm * 64 + mi * 16 + (lane >> 2) + half_ * 8;
                int bb = m >> 10;
                int s  = m & 1023;
                float y0 = (acc[mi][nf][half_ * 2 + 0] + b0) * scale;
                float y1 = (acc[mi][nf][half_ * 2 + 1] + b1) * scale;
                size_t o = (((size_t)(bb * NH + h) * SS + s) * DKV + d) >> 1;
                if (z == 0) {
                    uint32_t hp, lp;
                    split_pack2(y0, y1, hp, lp);
                    ((uint32_t*)g_qh)[o] = hp;
                    ((uint32_t*)g_ql)[o] = lp;
                } else {
                    uint32_t hp = round2h(y0, y1);
                    if (z == 1) ((uint32_t*)g_kf)[o] = hp;
                    else        ((uint32_t*)g_vf)[o] = hp;
                }
            }
        }
    }
}

// ---------------------------------------------------------------------------
// Attention via mma.sync fp16, 2-stage K/V pipeline, 2 CTAs/SM.  (R9 config)
// QK: Q hi/lo x K (2 products, exp-amplified so kept accurate).
// PV: P rounded to fp16, single product.
// ---------------------------------------------------------------------------
#define AST 32768          // stage: K 16K | V 16K
#define OS0 32768          // Qh 16K | Ql 16K
#define ATTN_SMEM (OS0 + 2 * AST)   // 98304

__global__ __launch_bounds__(256, 2)
void attn_mma_kernel(float* __restrict__ out)
{
    extern __shared__ char sm[];
    const uint32_t sb = s2u(sm);
    const int t    = threadIdx.x;
    const int w    = t >> 5;
    const int lane = t & 31;
    const int bh   = blockIdx.y;
    const int q0   = blockIdx.x * 128;

    const __half* Qh = g_qh + (size_t)bh * SS * DKV;
    const __half* Ql = g_ql + (size_t)bh * SS * DKV;
    const __half* Kf = g_kf + (size_t)bh * SS * DKV;
    const __half* Vf = g_vf + (size_t)bh * SS * DKV;

    // Q tiles (once)
    #pragma unroll
    for (int r_ = 0; r_ < 4; r_++) {
        int idx = t + r_ * 256;
        int row = idx >> 3;
        int ch  = idx & 7;
        uint32_t so = (uint32_t)(row * 128) + ((ch ^ (row & 7)) * 16);
        cp16(sb + so,          Qh + (size_t)(q0 + row) * DKV + ch * 8);
        cp16(sb + 16384 + so,  Ql + (size_t)(q0 + row) * DKV + ch * 8);
    }
    CP_COMMIT();

    #define A_LOAD_STAGE(c, stg) do {                                          \
        const uint32_t base_ = sb + OS0 + (stg) * AST;                         \
        const int kt_ = (c) * 128;                                             \
        _Pragma("unroll")                                                      \
        for (int r_ = 0; r_ < 4; r_++) {                                       \
            int idx_ = t + r_ * 256;                                           \
            int row_ = idx_ >> 3;                                              \
            int ch_  = idx_ & 7;                                               \
            uint32_t so_ = (uint32_t)(row_ * 128) + ((ch_ ^ (row_ & 7)) * 16); \
            size_t g_ = (size_t)(kt_ + row_) * DKV + ch_ * 8;                  \
            cp16(base_ + so_,          Kf + g_);                               \
            cp16(base_ + 16384 + so_,  Vf + g_);                               \
        }                                                                      \
        CP_COMMIT();                                                           \
    } while (0)

    A_LOAD_STAGE(0, 0);
    A_LOAD_STAGE(1, 1);

    float ctx[8][4];
    #pragma unroll
    for (int f = 0; f < 8; f++)
        #pragma unroll
        for (int r = 0; r < 4; r++) ctx[f][r] = 0.0f;
    float rs0 = 0.0f, rs1 = 0.0f;

    for (int c = 0; c < 8; c++) {
        CP_WAIT1();
        __syncthreads();
        const uint32_t kbase = sb + OS0 + (c & 1) * AST;
        const uint32_t vbase = kbase + 16384;

        #pragma unroll
        for (int half_ = 0; half_ < 2; half_++) {
            // ---- QK for 64-key half ----
            float S[8][4];
            #pragma unroll
            for (int f = 0; f < 8; f++)
                #pragma unroll
                for (int r = 0; r < 4; r++) S[f][r] = 0.0f;

            #pragma unroll
            for (int ks = 0; ks < 4; ks++) {
                const int chunk = 2 * ks + (lane >> 4);
                uint32_t aH[4], aL[4];
                {
                    int r = w * 16 + (lane & 15);
                    uint32_t so = sb + (uint32_t)(r * 128) + ((chunk ^ (r & 7)) * 16);
                    LDSM4(aH, so);
                    LDSM4(aL, so + 16384);
                }
                #pragma unroll
                for (int j = 0; j < 4; j++) {
                    int r = half_ * 64 + j * 16 + (lane & 15);
                    uint32_t so = kbase + (uint32_t)(r * 128) + ((chunk ^ (r & 7)) * 16);
                    uint32_t qk[4];
                    LDSM4(qk, so);
                    uint32_t b0[2] = {qk[0], qk[2]}, b1[2] = {qk[1], qk[3]};
                    MMA16816(S[2 * j],     aH, b0);
                    MMA16816(S[2 * j],     aL, b0);
                    MMA16816(S[2 * j + 1], aH, b1);
                    MMA16816(S[2 * j + 1], aL, b1);
                }
            }

            // ---- exp + rowsum + P round-to-fp16 + PV (single product) ----
            #pragma unroll
            for (int j = 0; j < 4; j++) {
                float e0 = __expf(S[2 * j][0]),     e1 = __expf(S[2 * j][1]);
                float e2 = __expf(S[2 * j][2]),     e3 = __expf(S[2 * j][3]);
                float e4 = __expf(S[2 * j + 1][0]), e5 = __expf(S[2 * j + 1][1]);
                float e6 = __expf(S[2 * j + 1][2]), e7 = __expf(S[2 * j + 1][3]);
                rs0 += (e0 + e1) + (e4 + e5);
                rs1 += (e2 + e3) + (e6 + e7);
                uint32_t aP[4];
                aP[0] = round2h(e0, e1);
                aP[1] = round2h(e2, e3);
                aP[2] = round2h(e4, e5);
                aP[3] = round2h(e6, e7);
                #pragma unroll
                for (int p = 0; p < 4; p++) {
                    int r  = half_ * 64 + j * 16 + (lane & 15);
                    int ch = p * 2 + (lane >> 4);
                    uint32_t so = vbase + (uint32_t)(r * 128) + ((ch ^ (r & 7)) * 16);
                    uint32_t vv[4];
                    LDSM4T(vv, so);
                    uint32_t b0[2] = {vv[0], vv[1]}, b1[2] = {vv[2], vv[3]};
                    MMA16816(ctx[2 * p],     aP, b0);
                    MMA16816(ctx[2 * p + 1], aP, b1);
                }
            }
        }

        __syncthreads();
        if (c < 6) { A_LOAD_STAGE(c + 2, c & 1); }
        else       { CP_COMMIT(); }
    }

    rs0 += __shfl_xor_sync(0xFFFFFFFF, rs0, 1);
    rs0 += __shfl_xor_sync(0xFFFFFFFF, rs0, 2);
    rs1 += __shfl_xor_sync(0xFFFFFFFF, rs1, 1);
    rs1 += __shfl_xor_sync(0xFFFFFFFF, rs1, 2);
    const float inv0 = 1.0f / (rs0 + 1e-8f);
    const float inv1 = 1.0f / (rs1 + 1e-8f);

    const int bb = bh >> 4;
    const int h  = bh & 15;
    const int sLo = q0 + w * 16 + (lane >> 2);
    #pragma unroll
    for (int f = 0; f < 8; f++) {
        int d0 = f * 8 + (lane & 3) * 2;
        float2 v0, v1;
        v0.x = ctx[f][0] * inv0; v0.y = ctx[f][1] * inv0;
        v1.x = ctx[f][2] * inv1; v1.y = ctx[f][3] * inv1;
        *(float2*)&out[((size_t)(bb * SS + sLo) * DMODEL) + h * DKV + d0]     = v0;
        *(float2*)&out[((size_t)(bb * SS + sLo + 8) * DMODEL) + h * DKV + d0] = v1;
    }
}

// ---------------------------------------------------------------------------
extern "C" void kernel_launch(void* const* d_in, const int* in_sizes, int n_in,
                              void* d_out, int out_size)
{
    const float* Q  = (const float*)d_in[0];
    const float* K  = (const float*)d_in[1];
    const float* V  = (const float*)d_in[2];
    const float* Wq = (const float*)d_in[3];
    const float* bq = (const float*)d_in[4];
    const float* Wk = (const float*)d_in[5];
    const float* bk = (const float*)d_in[6];
    const float* Wv = (const float*)d_in[7];
    const float* bv = (const float*)d_in[8];
    float* out = (float*)d_out;

    cudaFuncSetAttribute(proj_mma_kernel,
                         cudaFuncAttributeMaxDynamicSharedMemorySize, PROJ_SMEM);
    cudaFuncSetAttribute(attn_mma_kernel,
                         cudaFuncAttributeMaxDynamicSharedMemorySize, ATTN_SMEM);

    convert_x_kernel<<<dim3(MTOT * DMODEL / 1024, 3), 256>>>(Q, K, V);
    conv_w_kernel<<<dim3(32, 32, 3), dim3(32, 8)>>>(Wq, Wk, Wv);

    dim3 pg(MTOT / 128, DMODEL / 128, 3);
    proj_mma_kernel<<<pg, 256, PROJ_SMEM>>>(bq, bk, bv);

    dim3 ag(SS / 128, BB * NH);
    attn_mma_kernel<<<ag, 256, ATTN_SMEM>>>(out);
}

// round 12
// speedup vs baseline: 1.6526x; 1.1151x over previous
#include <cuda_runtime.h>
#include <cuda_fp16.h>
#include <cstdint>

#define BB 8
#define SS 1024
#define NH 16
#define DKV 64
#define DMODEL 1024
#define MTOT (BB*SS)

// X rounded to fp16; weights rounded to fp16, transposed [n][k]
__device__ __half g_x[3][MTOT*DMODEL];
__device__ __half g_wt[3][DMODEL*DMODEL];

// projected tensors, [bh][s][d]; q pre-scaled by log2(e)/8
__device__ __half g_q[BB*NH*SS*DKV];
__device__ __half g_kf[BB*NH*SS*DKV];
__device__ __half g_vf[BB*NH*SS*DKV];

static __device__ __forceinline__ uint32_t s2u(const void* p) {
    uint32_t a;
    asm("{ .reg .u64 t; cvta.to.shared.u64 t, %1; cvt.u32.u64 %0, t; }"
        : "=r"(a) : "l"(p));
    return a;
}

static __device__ __forceinline__ void cp16(uint32_t s, const void* g) {
    asm volatile("cp.async.cg.shared.global [%0], [%1], 16;" :: "r"(s), "l"(g));
}
#define CP_COMMIT() asm volatile("cp.async.commit_group;" ::: "memory")
#define CP_WAIT2()  asm volatile("cp.async.wait_group 2;" ::: "memory")

#define LDSM4(r, addr) \
    asm volatile("ldmatrix.sync.aligned.m8n8.x4.shared.b16 {%0,%1,%2,%3}, [%4];" \
        : "=r"((r)[0]), "=r"((r)[1]), "=r"((r)[2]), "=r"((r)[3]) : "r"(addr))

#define LDSM4T(r, addr) \
    asm volatile("ldmatrix.sync.aligned.m8n8.x4.trans.shared.b16 {%0,%1,%2,%3}, [%4];" \
        : "=r"((r)[0]), "=r"((r)[1]), "=r"((r)[2]), "=r"((r)[3]) : "r"(addr))

#define MMA16816(d, a, b) \
    asm volatile("mma.sync.aligned.m16n8k16.row.col.f32.f16.f16.f32 " \
        "{%0,%1,%2,%3}, {%4,%5,%6,%7}, {%8,%9}, {%0,%1,%2,%3};" \
        : "+f"((d)[0]), "+f"((d)[1]), "+f"((d)[2]), "+f"((d)[3]) \
        : "r"((a)[0]), "r"((a)[1]), "r"((a)[2]), "r"((a)[3]), \
          "r"((b)[0]), "r"((b)[1]))

static __device__ __forceinline__ uint32_t round2h(float x, float y) {
    __half2 h = __float22half2_rn(make_float2(x, y));
    return *(uint32_t*)&h;
}

static __device__ __forceinline__ float ex2(float x) {
    float y;
    asm("ex2.approx.f32 %0, %1;" : "=f"(y) : "f"(x));
    return y;
}

// q scale: (1/8) * log2(e)  -> scores arrive in log2 domain, P = 2^s
#define QSCALE 0.18033688011112042f

// ---------------------------------------------------------------------------
// Prep 1: X -> fp16 (rounded), row-major [8192, 1024]
// ---------------------------------------------------------------------------
__global__ __launch_bounds__(256)
void convert_x_kernel(const float* __restrict__ Q, const float* __restrict__ K,
                      const float* __restrict__ V)
{
    const int z = blockIdx.y;
    const float* X = (z == 0) ? Q : (z == 1) ? K : V;
    size_t i = ((size_t)blockIdx.x * 256 + threadIdx.x) * 4;
    float4 v = *(const float4*)(X + i);
    uint2 h;
    h.x = round2h(v.x, v.y);
    h.y = round2h(v.z, v.w);
    *(uint2*)&g_x[z][i] = h;
}

// ---------------------------------------------------------------------------
// Prep 2: W [k][n] -> Wt fp16 (rounded) [n][k]
// ---------------------------------------------------------------------------
__global__ __launch_bounds__(256)
void conv_w_kernel(const float* __restrict__ Wq, const float* __restrict__ Wk,
                   const float* __restrict__ Wv)
{
    const int z = blockIdx.z;
    const float* W = (z == 0) ? Wq : (z == 1) ? Wk : Wv;
    __shared__ float tile[32][33];
    const int tx = threadIdx.x;
    const int ty = threadIdx.y;
    const int n0 = blockIdx.x * 32;
    const int k0 = blockIdx.y * 32;
    #pragma unroll
    for (int i = 0; i < 4; i++)
        tile[ty + i * 8][tx] = W[(size_t)(k0 + ty + i * 8) * DMODEL + n0 + tx];
    __syncthreads();
    #pragma unroll
    for (int i = 0; i < 4; i++) {
        int n = ty + i * 8;
        g_wt[z][(size_t)(n0 + n) * DMODEL + k0 + tx] = __float2half_rn(tile[tx][n]);
    }
}

// ---------------------------------------------------------------------------
// mma.sync fp16 projection GEMM (single product), 3-stage cp.async, 2 CTAs/SM.
// ---------------------------------------------------------------------------
#define PSTAGE 32768   // X 16K | W 16K
#define PROJ_SMEM (1024 + 3 * PSTAGE)   // 99328

__global__ __launch_bounds__(256, 2)
void proj_mma_kernel(const float* __restrict__ bq, const float* __restrict__ bk,
                     const float* __restrict__ bv)
{
    extern __shared__ char sm[];
    const uint32_t sb = s2u(sm);
    const int t    = threadIdx.x;
    const int wid  = t >> 5;
    const int lane = t & 31;
    const int bm   = blockIdx.x * 128;
    const int bn   = blockIdx.y * 128;
    const int z    = blockIdx.z;

    const float* bias = (z == 0) ? bq : (z == 1) ? bk : bv;
    const float scale = (z == 0) ? QSCALE : 1.0f;
    const __half* Xf = g_x[z];
    const __half* Wt = g_wt[z];
    __half* Outp = (z == 0) ? g_q : (z == 1) ? g_kf : g_vf;

    float* biasS = (float*)sm;
    if (t < 128) biasS[t] = bias[bn + t];

    const int wm = wid >> 2;
    const int wn = wid & 3;

    float acc[4][4][4];
    #pragma unroll
    for (int i = 0; i < 4; i++)
        #pragma unroll
        for (int j = 0; j < 4; j++)
            #pragma unroll
            for (int r = 0; r < 4; r++) acc[i][j][r] = 0.0f;

    #define LOAD_STAGE(c, buf) do {                                            \
        const uint32_t base_ = sb + 1024 + (buf) * PSTAGE;                     \
        const int k0_ = (c) * 64;                                              \
        _Pragma("unroll")                                                      \
        for (int r_ = 0; r_ < 4; r_++) {                                       \
            int idx_ = t + r_ * 256;                                           \
            int row_ = idx_ >> 3;                                              \
            int ch_  = idx_ & 7;                                               \
            uint32_t so_ = (uint32_t)(row_ * 128) + ((ch_ ^ (row_ & 7)) * 16); \
            size_t ga_ = (size_t)(bm + row_) * DMODEL + k0_ + ch_ * 8;         \
            size_t gb_ = (size_t)(bn + row_) * DMODEL + k0_ + ch_ * 8;         \
            cp16(base_ + so_,          Xf + ga_);                              \
            cp16(base_ + 16384 + so_,  Wt + gb_);                              \
        }                                                                      \
        CP_COMMIT();                                                           \
    } while (0)

    LOAD_STAGE(0, 0);
    LOAD_STAGE(1, 1);
    LOAD_STAGE(2, 2);

    for (int c = 0; c < 16; c++) {
        CP_WAIT2();
        __syncthreads();
        const int bufc = c % 3;
        const uint32_t base = sb + 1024 + bufc * PSTAGE;
        #pragma unroll
        for (int ks = 0; ks < 4; ks++) {
            uint32_t aF[4][4], bF[4][2];
            const int chunk = 2 * ks + (lane >> 4);
            #pragma unroll
            for (int mi = 0; mi < 4; mi++) {
                int r = wm * 64 + mi * 16 + (lane & 15);
                uint32_t so = base + (uint32_t)(r * 128) + ((chunk ^ (r & 7)) * 16);
                LDSM4(aF[mi], so);
            }
            #pragma unroll
            for (int p = 0; p < 2; p++) {
                int r = wn * 32 + p * 16 + (lane & 15);
                uint32_t so = base + 16384 + (uint32_t)(r * 128) + ((chunk ^ (r & 7)) * 16);
                uint32_t q[4];
                LDSM4(q, so);
                bF[p * 2][0] = q[0]; bF[p * 2][1] = q[2];
                bF[p * 2 + 1][0] = q[1]; bF[p * 2 + 1][1] = q[3];
            }
            #pragma unroll
            for (int mi = 0; mi < 4; mi++)
                #pragma unroll
                for (int nf = 0; nf < 4; nf++)
                    MMA16816(acc[mi][nf], aF[mi], bF[nf]);
        }
        __syncthreads();
        if (c < 13) { LOAD_STAGE(c + 3, bufc); }
        else        { CP_COMMIT(); }
    }

    // epilogue -> [bh][s][d] fp16 (q pre-scaled by QSCALE)
    #pragma unroll
    for (int mi = 0; mi < 4; mi++) {
        #pragma unroll
        for (int nf = 0; nf < 4; nf++) {
            int nloc = wn * 32 + nf * 8 + (lane & 3) * 2;
            int n = bn + nloc;
            int h = n >> 6;
            int d = n & 63;
            float b0 = biasS[nloc], b1 = biasS[nloc + 1];
            #pragma unroll
            for (int half_ = 0; half_ < 2; half_++) {
                int m = bm + wm * 64 + mi * 16 + (lane >> 2) + half_ * 8;
                int bb = m >> 10;
                int s  = m & 1023;
                float y0 = (acc[mi][nf][half_ * 2 + 0] + b0) * scale;
                float y1 = (acc[mi][nf][half_ * 2 + 1] + b1) * scale;
                size_t o = (((size_t)(bb * NH + h) * SS + s) * DKV + d) >> 1;
                ((uint32_t*)Outp)[o] = round2h(y0, y1);
            }
        }
    }
}

// ---------------------------------------------------------------------------
// Attention via mma.sync fp16, all single-product, 3-stage K/V, 2 CTAs/SM.
// QK: q (log2-scaled) x K -> S in log2 domain; P = ex2(S) fp32, rounded to
// fp16 for PV. Rowsum in fp32 via register accumulation + quad shfl.
// ---------------------------------------------------------------------------
#define AST 32768          // stage: K 16K | V 16K
#define OS0 16384          // Q 16K
#define ATTN_SMEM (OS0 + 3 * AST)   // 114688

__global__ __launch_bounds__(256, 2)
void attn_mma_kernel(float* __restrict__ out)
{
    extern __shared__ char sm[];
    const uint32_t sb = s2u(sm);
    const int t    = threadIdx.x;
    const int w    = t >> 5;
    const int lane = t & 31;
    const int bh   = blockIdx.y;
    const int q0   = blockIdx.x * 128;

    const __half* Qf = g_q  + (size_t)bh * SS * DKV;
    const __half* Kf = g_kf + (size_t)bh * SS * DKV;
    const __half* Vf = g_vf + (size_t)bh * SS * DKV;

    // Q tile (once): 128 rows x 128B
    #pragma unroll
    for (int r_ = 0; r_ < 4; r_++) {
        int idx = t + r_ * 256;
        int row = idx >> 3;
        int ch  = idx & 7;
        uint32_t so = (uint32_t)(row * 128) + ((ch ^ (row & 7)) * 16);
        cp16(sb + so, Qf + (size_t)(q0 + row) * DKV + ch * 8);
    }
    CP_COMMIT();

    #define A_LOAD_STAGE(c, stg) do {                                          \
        const uint32_t base_ = sb + OS0 + (stg) * AST;                         \
        const int kt_ = (c) * 128;                                             \
        _Pragma("unroll")                                                      \
        for (int r_ = 0; r_ < 4; r_++) {                                       \
            int idx_ = t + r_ * 256;                                           \
            int row_ = idx_ >> 3;                                              \
            int ch_  = idx_ & 7;                                               \
            uint32_t so_ = (uint32_t)(row_ * 128) + ((ch_ ^ (row_ & 7)) * 16); \
            size_t g_ = (size_t)(kt_ + row_) * DKV + ch_ * 8;                  \
            cp16(base_ + so_,          Kf + g_);                               \
            cp16(base_ + 16384 + so_,  Vf + g_);                               \
        }                                                                      \
        CP_COMMIT();                                                           \
    } while (0)

    A_LOAD_STAGE(0, 0);
    A_LOAD_STAGE(1, 1);
    A_LOAD_STAGE(2, 2);

    float ctx[8][4];
    #pragma unroll
    for (int f = 0; f < 8; f++)
        #pragma unroll
        for (int r = 0; r < 4; r++) ctx[f][r] = 0.0f;
    float rs0 = 0.0f, rs1 = 0.0f;

    for (int c = 0; c < 8; c++) {
        CP_WAIT2();        // Q + stage c complete (<=2 newer groups pending)
        __syncthreads();
        const int bufc = c % 3;
        const uint32_t kbase = sb + OS0 + bufc * AST;
        const uint32_t vbase = kbase + 16384;

        #pragma unroll
        for (int half_ = 0; half_ < 2; half_++) {
            // ---- QK (single product) for 64-key half ----
            float S[8][4];
            #pragma unroll
            for (int f = 0; f < 8; f++)
                #pragma unroll
                for (int r = 0; r < 4; r++) S[f][r] = 0.0f;

            #pragma unroll
            for (int ks = 0; ks < 4; ks++) {
                const int chunk = 2 * ks + (lane >> 4);
                uint32_t aF[4];
                {
                    int r = w * 16 + (lane & 15);
                    uint32_t so = sb + (uint32_t)(r * 128) + ((chunk ^ (r & 7)) * 16);
                    LDSM4(aF, so);
                }
                #pragma unroll
                for (int j = 0; j < 4; j++) {
                    int r = half_ * 64 + j * 16 + (lane & 15);
                    uint32_t so = kbase + (uint32_t)(r * 128) + ((chunk ^ (r & 7)) * 16);
                    uint32_t qk[4];
                    LDSM4(qk, so);
                    uint32_t b0[2] = {qk[0], qk[2]}, b1[2] = {qk[1], qk[3]};
                    MMA16816(S[2 * j],     aF, b0);
                    MMA16816(S[2 * j + 1], aF, b1);
                }
            }

            // ---- P = 2^S, rowsum, round P to fp16, PV (single product) ----
            #pragma unroll
            for (int j = 0; j < 4; j++) {
                float e0 = ex2(S[2 * j][0]),     e1 = ex2(S[2 * j][1]);
                float e2 = ex2(S[2 * j][2]),     e3 = ex2(S[2 * j][3]);
                float e4 = ex2(S[2 * j + 1][0]), e5 = ex2(S[2 * j + 1][1]);
                float e6 = ex2(S[2 * j + 1][2]), e7 = ex2(S[2 * j + 1][3]);
                rs0 += (e0 + e1) + (e4 + e5);
                rs1 += (e2 + e3) + (e6 + e7);
                uint32_t aP[4];
                aP[0] = round2h(e0, e1);
                aP[1] = round2h(e2, e3);
                aP[2] = round2h(e4, e5);
                aP[3] = round2h(e6, e7);
                #pragma unroll
                for (int p = 0; p < 4; p++) {
                    int r  = half_ * 64 + j * 16 + (lane & 15);
                    int ch = p * 2 + (lane >> 4);
                    uint32_t so = vbase + (uint32_t)(r * 128) + ((ch ^ (r & 7)) * 16);
                    uint32_t vv[4];
                    LDSM4T(vv, so);
                    uint32_t b0[2] = {vv[0], vv[1]}, b1[2] = {vv[2], vv[3]};
                    MMA16816(ctx[2 * p],     aP, b0);
                    MMA16816(ctx[2 * p + 1], aP, b1);
                }
            }
        }

        __syncthreads();
        if (c < 5) { A_LOAD_STAGE(c + 3, bufc); }
        else       { CP_COMMIT(); }
    }

    rs0 += __shfl_xor_sync(0xFFFFFFFF, rs0, 1);
    rs0 += __shfl_xor_sync(0xFFFFFFFF, rs0, 2);
    rs1 += __shfl_xor_sync(0xFFFFFFFF, rs1, 1);
    rs1 += __shfl_xor_sync(0xFFFFFFFF, rs1, 2);
    const float inv0 = 1.0f / (rs0 + 1e-8f);
    const float inv1 = 1.0f / (rs1 + 1e-8f);

    const int bb = bh >> 4;
    const int h  = bh & 15;
    const int sLo = q0 + w * 16 + (lane >> 2);
    #pragma unroll
    for (int f = 0; f < 8; f++) {
        int d0 = f * 8 + (lane & 3) * 2;
        float2 v0, v1;
        v0.x = ctx[f][0] * inv0; v0.y = ctx[f][1] * inv0;
        v1.x = ctx[f][2] * inv1; v1.y = ctx[f][3] * inv1;
        *(float2*)&out[((size_t)(bb * SS + sLo) * DMODEL) + h * DKV + d0]     = v0;
        *(float2*)&out[((size_t)(bb * SS + sLo + 8) * DMODEL) + h * DKV + d0] = v1;
    }
}

// ---------------------------------------------------------------------------
extern "C" void kernel_launch(void* const* d_in, const int* in_sizes, int n_in,
                              void* d_out, int out_size)
{
    const float* Q  = (const float*)d_in[0];
    const float* K  = (const float*)d_in[1];
    const float* V  = (const float*)d_in[2];
    const float* Wq = (const float*)d_in[3];
    const float* bq = (const float*)d_in[4];
    const float* Wk = (const float*)d_in[5];
    const float* bk = (const float*)d_in[6];
    const float* Wv = (const float*)d_in[7];
    const float* bv = (const float*)d_in[8];
    float* out = (float*)d_out;

    cudaFuncSetAttribute(proj_mma_kernel,
                         cudaFuncAttributeMaxDynamicSharedMemorySize, PROJ_SMEM);
    cudaFuncSetAttribute(attn_mma_kernel,
                         cudaFuncAttributeMaxDynamicSharedMemorySize, ATTN_SMEM);

    convert_x_kernel<<<dim3(MTOT * DMODEL / 1024, 3), 256>>>(Q, K, V);
    conv_w_kernel<<<dim3(32, 32, 3), dim3(32, 8)>>>(Wq, Wk, Wv);

    dim3 pg(MTOT / 128, DMODEL / 128, 3);
    proj_mma_kernel<<<pg, 256, PROJ_SMEM>>>(bq, bk, bv);

    dim3 ag(SS / 128, BB * NH);
    attn_mma_kernel<<<ag, 256, ATTN_SMEM>>>(out);
}

// round 13
// speedup vs baseline: 1.7107x; 1.0352x over previous
#include <cuda_runtime.h>
#include <cuda_fp16.h>
#include <cstdint>

#define BB 8
#define SS 1024
#define NH 16
#define DKV 64
#define DMODEL 1024
#define MTOT (BB*SS)

// X rounded to fp16; weights rounded to fp16, transposed [n][k]
__device__ __half g_x[3][MTOT*DMODEL];
__device__ __half g_wt[3][DMODEL*DMODEL];

// projected tensors, [bh][s][d]; q pre-scaled by log2(e)/8
__device__ __half g_q[BB*NH*SS*DKV];
__device__ __half g_kf[BB*NH*SS*DKV];
__device__ __half g_vf[BB*NH*SS*DKV];

static __device__ __forceinline__ uint32_t s2u(const void* p) {
    uint32_t a;
    asm("{ .reg .u64 t; cvta.to.shared.u64 t, %1; cvt.u32.u64 %0, t; }"
        : "=r"(a) : "l"(p));
    return a;
}

static __device__ __forceinline__ void cp16(uint32_t s, const void* g) {
    asm volatile("cp.async.cg.shared.global [%0], [%1], 16;" :: "r"(s), "l"(g));
}
#define CP_COMMIT() asm volatile("cp.async.commit_group;" ::: "memory")
#define CP_WAIT2()  asm volatile("cp.async.wait_group 2;" ::: "memory")

#define LDSM4(r, addr) \
    asm volatile("ldmatrix.sync.aligned.m8n8.x4.shared.b16 {%0,%1,%2,%3}, [%4];" \
        : "=r"((r)[0]), "=r"((r)[1]), "=r"((r)[2]), "=r"((r)[3]) : "r"(addr))

#define LDSM4T(r, addr) \
    asm volatile("ldmatrix.sync.aligned.m8n8.x4.trans.shared.b16 {%0,%1,%2,%3}, [%4];" \
        : "=r"((r)[0]), "=r"((r)[1]), "=r"((r)[2]), "=r"((r)[3]) : "r"(addr))

#define MMA16816(d, a, b) \
    asm volatile("mma.sync.aligned.m16n8k16.row.col.f32.f16.f16.f32 " \
        "{%0,%1,%2,%3}, {%4,%5,%6,%7}, {%8,%9}, {%0,%1,%2,%3};" \
        : "+f"((d)[0]), "+f"((d)[1]), "+f"((d)[2]), "+f"((d)[3]) \
        : "r"((a)[0]), "r"((a)[1]), "r"((a)[2]), "r"((a)[3]), \
          "r"((b)[0]), "r"((b)[1]))

static __device__ __forceinline__ uint32_t round2h(float x, float y) {
    __half2 h = __float22half2_rn(make_float2(x, y));
    return *(uint32_t*)&h;
}

// q scale: (1/8) * log2(e)  -> scores arrive in log2 domain, P = 2^s
#define QSCALE 0.18033688011112042f

// ---------------------------------------------------------------------------
// Prep 1: X -> fp16 (rounded), row-major [8192, 1024]
// ---------------------------------------------------------------------------
__global__ __launch_bounds__(256)
void convert_x_kernel(const float* __restrict__ Q, const float* __restrict__ K,
                      const float* __restrict__ V)
{
    const int z = blockIdx.y;
    const float* X = (z == 0) ? Q : (z == 1) ? K : V;
    size_t i = ((size_t)blockIdx.x * 256 + threadIdx.x) * 4;
    float4 v = *(const float4*)(X + i);
    uint2 h;
    h.x = round2h(v.x, v.y);
    h.y = round2h(v.z, v.w);
    *(uint2*)&g_x[z][i] = h;
}

// ---------------------------------------------------------------------------
// Prep 2: W [k][n] -> Wt fp16 (rounded) [n][k]
// ---------------------------------------------------------------------------
__global__ __launch_bounds__(256)
void conv_w_kernel(const float* __restrict__ Wq, const float* __restrict__ Wk,
                   const float* __restrict__ Wv)
{
    const int z = blockIdx.z;
    const float* W = (z == 0) ? Wq : (z == 1) ? Wk : Wv;
    __shared__ float tile[32][33];
    const int tx = threadIdx.x;
    const int ty = threadIdx.y;
    const int n0 = blockIdx.x * 32;
    const int k0 = blockIdx.y * 32;
    #pragma unroll
    for (int i = 0; i < 4; i++)
        tile[ty + i * 8][tx] = W[(size_t)(k0 + ty + i * 8) * DMODEL + n0 + tx];
    __syncthreads();
    #pragma unroll
    for (int i = 0; i < 4; i++) {
        int n = ty + i * 8;
        g_wt[z][(size_t)(n0 + n) * DMODEL + k0 + tx] = __float2half_rn(tile[tx][n]);
    }
}

// ---------------------------------------------------------------------------
// mma.sync fp16 projection GEMM (single product), 3-stage cp.async, 2 CTAs/SM.
// ---------------------------------------------------------------------------
#define PSTAGE 32768   // X 16K | W 16K
#define PROJ_SMEM (1024 + 3 * PSTAGE)   // 99328

__global__ __launch_bounds__(256, 2)
void proj_mma_kernel(const float* __restrict__ bq, const float* __restrict__ bk,
                     const float* __restrict__ bv)
{
    extern __shared__ char sm[];
    const uint32_t sb = s2u(sm);
    const int t    = threadIdx.x;
    const int wid  = t >> 5;
    const int lane = t & 31;
    const int bm   = blockIdx.x * 128;
    const int bn   = blockIdx.y * 128;
    const int z    = blockIdx.z;

    const float* bias = (z == 0) ? bq : (z == 1) ? bk : bv;
    const float scale = (z == 0) ? QSCALE : 1.0f;
    const __half* Xf = g_x[z];
    const __half* Wt = g_wt[z];
    __half* Outp = (z == 0) ? g_q : (z == 1) ? g_kf : g_vf;

    float* biasS = (float*)sm;
    if (t < 128) biasS[t] = bias[bn + t];

    const int wm = wid >> 2;
    const int wn = wid & 3;

    float acc[4][4][4];
    #pragma unroll
    for (int i = 0; i < 4; i++)
        #pragma unroll
        for (int j = 0; j < 4; j++)
            #pragma unroll
            for (int r = 0; r < 4; r++) acc[i][j][r] = 0.0f;

    #define LOAD_STAGE(c, buf) do {                                            \
        const uint32_t base_ = sb + 1024 + (buf) * PSTAGE;                     \
        const int k0_ = (c) * 64;                                              \
        _Pragma("unroll")                                                      \
        for (int r_ = 0; r_ < 4; r_++) {                                       \
            int idx_ = t + r_ * 256;                                           \
            int row_ = idx_ >> 3;                                              \
            int ch_  = idx_ & 7;                                               \
            uint32_t so_ = (uint32_t)(row_ * 128) + ((ch_ ^ (row_ & 7)) * 16); \
            size_t ga_ = (size_t)(bm + row_) * DMODEL + k0_ + ch_ * 8;         \
            size_t gb_ = (size_t)(bn + row_) * DMODEL + k0_ + ch_ * 8;         \
            cp16(base_ + so_,          Xf + ga_);                              \
            cp16(base_ + 16384 + so_,  Wt + gb_);                              \
        }                                                                      \
        CP_COMMIT();                                                           \
    } while (0)

    LOAD_STAGE(0, 0);
    LOAD_STAGE(1, 1);
    LOAD_STAGE(2, 2);

    for (int c = 0; c < 16; c++) {
        CP_WAIT2();
        __syncthreads();
        const int bufc = c % 3;
        const uint32_t base = sb + 1024 + bufc * PSTAGE;
        #pragma unroll
        for (int ks = 0; ks < 4; ks++) {
            uint32_t aF[4][4], bF[4][2];
            const int chunk = 2 * ks + (lane >> 4);
            #pragma unroll
            for (int mi = 0; mi < 4; mi++) {
                int r = wm * 64 + mi * 16 + (lane & 15);
                uint32_t so = base + (uint32_t)(r * 128) + ((chunk ^ (r & 7)) * 16);
                LDSM4(aF[mi], so);
            }
            #pragma unroll
            for (int p = 0; p < 2; p++) {
                int r = wn * 32 + p * 16 + (lane & 15);
                uint32_t so = base + 16384 + (uint32_t)(r * 128) + ((chunk ^ (r & 7)) * 16);
                uint32_t q[4];
                LDSM4(q, so);
                bF[p * 2][0] = q[0]; bF[p * 2][1] = q[2];
                bF[p * 2 + 1][0] = q[1]; bF[p * 2 + 1][1] = q[3];
            }
            #pragma unroll
            for (int mi = 0; mi < 4; mi++)
                #pragma unroll
                for (int nf = 0; nf < 4; nf++)
                    MMA16816(acc[mi][nf], aF[mi], bF[nf]);
        }
        __syncthreads();
        if (c < 13) { LOAD_STAGE(c + 3, bufc); }
        else        { CP_COMMIT(); }
    }

    // epilogue -> [bh][s][d] fp16 (q pre-scaled by QSCALE)
    #pragma unroll
    for (int mi = 0; mi < 4; mi++) {
        #pragma unroll
        for (int nf = 0; nf < 4; nf++) {
            int nloc = wn * 32 + nf * 8 + (lane & 3) * 2;
            int n = bn + nloc;
            int h = n >> 6;
            int d = n & 63;
            float b0 = biasS[nloc], b1 = biasS[nloc + 1];
            #pragma unroll
            for (int half_ = 0; half_ < 2; half_++) {
                int m = bm + wm * 64 + mi * 16 + (lane >> 2) + half_ * 8;
                int bb = m >> 10;
                int s  = m & 1023;
                float y0 = (acc[mi][nf][half_ * 2 + 0] + b0) * scale;
                float y1 = (acc[mi][nf][half_ * 2 + 1] + b1) * scale;
                size_t o = (((size_t)(bb * NH + h) * SS + s) * DKV + d) >> 1;
                ((uint32_t*)Outp)[o] = round2h(y0, y1);
            }
        }
    }
}

// ---------------------------------------------------------------------------
// Attention via mma.sync fp16, all single-product, 3-stage K/V, 2 CTAs/SM.
// Q fragments hoisted out of the mainloop (Q smem is immutable).
// P = ex2.approx.f16x2 on fp16-rounded log2 scores -> packed fp16 P frags
// directly; rowsum via HADD2 + fp32 accumulate.
// ---------------------------------------------------------------------------
#define AST 32768          // stage: K 16K | V 16K
#define OS0 16384          // Q 16K
#define ATTN_SMEM (OS0 + 3 * AST)   // 114688

__global__ __launch_bounds__(256, 2)
void attn_mma_kernel(float* __restrict__ out)
{
    extern __shared__ char sm[];
    const uint32_t sb = s2u(sm);
    const int t    = threadIdx.x;
    const int w    = t >> 5;
    const int lane = t & 31;
    const int bh   = blockIdx.y;
    const int q0   = blockIdx.x * 128;

    const __half* Qf = g_q  + (size_t)bh * SS * DKV;
    const __half* Kf = g_kf + (size_t)bh * SS * DKV;
    const __half* Vf = g_vf + (size_t)bh * SS * DKV;

    // Q tile (once): 128 rows x 128B
    #pragma unroll
    for (int r_ = 0; r_ < 4; r_++) {
        int idx = t + r_ * 256;
        int row = idx >> 3;
        int ch  = idx & 7;
        uint32_t so = (uint32_t)(row * 128) + ((ch ^ (row & 7)) * 16);
        cp16(sb + so, Qf + (size_t)(q0 + row) * DKV + ch * 8);
    }
    CP_COMMIT();

    #define A_LOAD_STAGE(c, stg) do {                                          \
        const uint32_t base_ = sb + OS0 + (stg) * AST;                         \
        const int kt_ = (c) * 128;                                             \
        _Pragma("unroll")                                                      \
        for (int r_ = 0; r_ < 4; r_++) {                                       \
            int idx_ = t + r_ * 256;                                           \
            int row_ = idx_ >> 3;                                              \
            int ch_  = idx_ & 7;                                               \
            uint32_t so_ = (uint32_t)(row_ * 128) + ((ch_ ^ (row_ & 7)) * 16); \
            size_t g_ = (size_t)(kt_ + row_) * DKV + ch_ * 8;                  \
            cp16(base_ + so_,          Kf + g_);                               \
            cp16(base_ + 16384 + so_,  Vf + g_);                               \
        }                                                                      \
        CP_COMMIT();                                                           \
    } while (0)

    A_LOAD_STAGE(0, 0);
    A_LOAD_STAGE(1, 1);
    A_LOAD_STAGE(2, 2);

    // wait for Q + stage 0, then hoist Q fragments into registers
    CP_WAIT2();
    __syncthreads();
    uint32_t qfr[4][4];
    #pragma unroll
    for (int ks = 0; ks < 4; ks++) {
        const int chunk = 2 * ks + (lane >> 4);
        int r = w * 16 + (lane & 15);
        uint32_t so = sb + (uint32_t)(r * 128) + ((chunk ^ (r & 7)) * 16);
        LDSM4(qfr[ks], so);
    }

    float ctx[8][4];
    #pragma unroll
    for (int f = 0; f < 8; f++)
        #pragma unroll
        for (int r = 0; r < 4; r++) ctx[f][r] = 0.0f;
    float rs0 = 0.0f, rs1 = 0.0f;

    for (int c = 0; c < 8; c++) {
        CP_WAIT2();
        __syncthreads();
        const int bufc = c % 3;
        const uint32_t kbase = sb + OS0 + bufc * AST;
        const uint32_t vbase = kbase + 16384;

        #pragma unroll
        for (int half_ = 0; half_ < 2; half_++) {
            // ---- QK (single product) for 64-key half ----
            float S[8][4];
            #pragma unroll
            for (int f = 0; f < 8; f++)
                #pragma unroll
                for (int r = 0; r < 4; r++) S[f][r] = 0.0f;

            #pragma unroll
            for (int ks = 0; ks < 4; ks++) {
                const int chunk = 2 * ks + (lane >> 4);
                #pragma unroll
                for (int j = 0; j < 4; j++) {
                    int r = half_ * 64 + j * 16 + (lane & 15);
                    uint32_t so = kbase + (uint32_t)(r * 128) + ((chunk ^ (r & 7)) * 16);
                    uint32_t qk[4];
                    LDSM4(qk, so);
                    uint32_t b0[2] = {qk[0], qk[2]}, b1[2] = {qk[1], qk[3]};
                    MMA16816(S[2 * j],     qfr[ks], b0);
                    MMA16816(S[2 * j + 1], qfr[ks], b1);
                }
            }

            // ---- round S to fp16x2, P = ex2.f16x2, HADD2 rowsum, PV ----
            #pragma unroll
            for (int j = 0; j < 4; j++) {
                uint32_t sp0 = round2h(S[2 * j][0],     S[2 * j][1]);
                uint32_t sp1 = round2h(S[2 * j][2],     S[2 * j][3]);
                uint32_t sp2 = round2h(S[2 * j + 1][0], S[2 * j + 1][1]);
                uint32_t sp3 = round2h(S[2 * j + 1][2], S[2 * j + 1][3]);
                uint32_t aP[4];
                asm("ex2.approx.f16x2 %0, %1;" : "=r"(aP[0]) : "r"(sp0));
                asm("ex2.approx.f16x2 %0, %1;" : "=r"(aP[1]) : "r"(sp1));
                asm("ex2.approx.f16x2 %0, %1;" : "=r"(aP[2]) : "r"(sp2));
                asm("ex2.approx.f16x2 %0, %1;" : "=r"(aP[3]) : "r"(sp3));
                uint32_t t0, t1;
                asm("add.rn.f16x2 %0, %1, %2;" : "=r"(t0) : "r"(aP[0]), "r"(aP[2]));
                asm("add.rn.f16x2 %0, %1, %2;" : "=r"(t1) : "r"(aP[1]), "r"(aP[3]));
                float2 f0 = __half22float2(*(__half2*)&t0);
                float2 f1 = __half22float2(*(__half2*)&t1);
                rs0 += f0.x + f0.y;
                rs1 += f1.x + f1.y;
                #pragma unroll
                for (int p = 0; p < 4; p++) {
                    int r  = half_ * 64 + j * 16 + (lane & 15);
                    int ch = p * 2 + (lane >> 4);
                    uint32_t so = vbase + (uint32_t)(r * 128) + ((ch ^ (r & 7)) * 16);
                    uint32_t vv[4];
                    LDSM4T(vv, so);
                    uint32_t b0[2] = {vv[0], vv[1]}, b1[2] = {vv[2], vv[3]};
                    MMA16816(ctx[2 * p],     aP, b0);
                    MMA16816(ctx[2 * p + 1], aP, b1);
                }
            }
        }

        __syncthreads();
        if (c < 5) { A_LOAD_STAGE(c + 3, bufc); }
        else       { CP_COMMIT(); }
    }

    rs0 += __shfl_xor_sync(0xFFFFFFFF, rs0, 1);
    rs0 += __shfl_xor_sync(0xFFFFFFFF, rs0, 2);
    rs1 += __shfl_xor_sync(0xFFFFFFFF, rs1, 1);
    rs1 += __shfl_xor_sync(0xFFFFFFFF, rs1, 2);
    const float inv0 = 1.0f / (rs0 + 1e-8f);
    const float inv1 = 1.0f / (rs1 + 1e-8f);

    const int bb = bh >> 4;
    const int h  = bh & 15;
    const int sLo = q0 + w * 16 + (lane >> 2);
    #pragma unroll
    for (int f = 0; f < 8; f++) {
        int d0 = f * 8 + (lane & 3) * 2;
        float2 v0, v1;
        v0.x = ctx[f][0] * inv0; v0.y = ctx[f][1] * inv0;
        v1.x = ctx[f][2] * inv1; v1.y = ctx[f][3] * inv1;
        *(float2*)&out[((size_t)(bb * SS + sLo) * DMODEL) + h * DKV + d0]     = v0;
        *(float2*)&out[((size_t)(bb * SS + sLo + 8) * DMODEL) + h * DKV + d0] = v1;
    }
}

// ---------------------------------------------------------------------------
extern "C" void kernel_launch(void* const* d_in, const int* in_sizes, int n_in,
                              void* d_out, int out_size)
{
    const float* Q  = (const float*)d_in[0];
    const float* K  = (const float*)d_in[1];
    const float* V  = (const float*)d_in[2];
    const float* Wq = (const float*)d_in[3];
    const float* bq = (const float*)d_in[4];
    const float* Wk = (const float*)d_in[5];
    const float* bk = (const float*)d_in[6];
    const float* Wv = (const float*)d_in[7];
    const float* bv = (const float*)d_in[8];
    float* out = (float*)d_out;

    cudaFuncSetAttribute(proj_mma_kernel,
                         cudaFuncAttributeMaxDynamicSharedMemorySize, PROJ_SMEM);
    cudaFuncSetAttribute(attn_mma_kernel,
                         cudaFuncAttributeMaxDynamicSharedMemorySize, ATTN_SMEM);

    convert_x_kernel<<<dim3(MTOT * DMODEL / 1024, 3), 256>>>(Q, K, V);
    conv_w_kernel<<<dim3(32, 32, 3), dim3(32, 8)>>>(Wq, Wk, Wv);

    dim3 pg(MTOT / 128, DMODEL / 128, 3);
    proj_mma_kernel<<<pg, 256, PROJ_SMEM>>>(bq, bk, bv);

    dim3 ag(SS / 128, BB * NH);
    attn_mma_kernel<<<ag, 256, ATTN_SMEM>>>(out);
}